// round 1
// baseline (speedup 1.0000x reference)
#include <cuda_runtime.h>
#include <math.h>

#define BB 4
#define SS 2048
#define DD 1024
#define HH 16
#define HDD 64
#define M_TOT (BB*SS)          // 8192
#define N_QKV (3*DD)           // 3072

// Scratch (device globals: allocation-free)
__device__ float g_qkv[(size_t)M_TOT * N_QKV];   // [B*S, 3D]
__device__ float g_y[(size_t)M_TOT * DD];        // [B*S, D] attention output

// ---------------------------------------------------------------------------
// SGEMM with fused bias: C[M,N] = A[M,K] @ W[K,N] + bias[N]
// 128x128 block tile, BK=8, 8x8 per-thread micro-tile, 256 threads.
// ---------------------------------------------------------------------------
__global__ void __launch_bounds__(256) sgemm_bias(
    const float* __restrict__ A, const float* __restrict__ W,
    const float* __restrict__ bias, float* __restrict__ C,
    int M, int N, int K)
{
    __shared__ float As[8][132];   // transposed A tile, padded (kills store conflicts)
    __shared__ float Bs[8][128];

    const int tid = threadIdx.x;
    const int bm = blockIdx.y * 128;
    const int bn = blockIdx.x * 128;
    const int tx = tid & 15, ty = tid >> 4;

    const int arow = tid >> 1, acol = (tid & 1) * 4;
    const int brow = tid >> 5, bcol = (tid & 31) * 4;

    const float* Ap = A + (size_t)(bm + arow) * K + acol;
    const float* Bp = W + (size_t)brow * N + bn + bcol;

    float acc[8][8];
    #pragma unroll
    for (int i = 0; i < 8; i++)
        #pragma unroll
        for (int j = 0; j < 8; j++) acc[i][j] = 0.0f;

    for (int k0 = 0; k0 < K; k0 += 8) {
        float4 av = *(const float4*)(Ap + k0);
        float4 bv = *(const float4*)(Bp + (size_t)k0 * N);
        As[acol + 0][arow] = av.x;
        As[acol + 1][arow] = av.y;
        As[acol + 2][arow] = av.z;
        As[acol + 3][arow] = av.w;
        *(float4*)(&Bs[brow][bcol]) = bv;
        __syncthreads();

        #pragma unroll
        for (int kk = 0; kk < 8; kk++) {
            float a[8], b[8];
            #pragma unroll
            for (int i = 0; i < 8; i++) a[i] = As[kk][ty * 8 + i];
            #pragma unroll
            for (int j = 0; j < 8; j++) b[j] = Bs[kk][tx * 8 + j];
            #pragma unroll
            for (int i = 0; i < 8; i++)
                #pragma unroll
                for (int j = 0; j < 8; j++)
                    acc[i][j] += a[i] * b[j];
        }
        __syncthreads();
    }

    #pragma unroll
    for (int i = 0; i < 8; i++) {
        size_t row = (size_t)(bm + ty * 8 + i);
        float* Cp = C + row * N + bn + tx * 8;
        #pragma unroll
        for (int j = 0; j < 8; j++)
            Cp[j] = acc[i][j] + bias[bn + tx * 8 + j];
    }
}

// ---------------------------------------------------------------------------
// Flash attention (causal), fp32.
// Grid: (S/64, H, B). Block: 256 threads (tx = tid&15, ty = tid>>4).
// Each block: 64 query rows x HD=64. Iterates key blocks kb = 0..qb.
// Per-thread micro-tile: rows r0..r0+3 (r0 = ty*4), cols tx + 16*j (cyclic).
// smem (dynamic): Qs[64][65], Kt[64][65] (transposed K), Vs[64][64], Ps[64][65]
// ---------------------------------------------------------------------------
#define QS_OFF   0
#define KT_OFF   (64 * 65)
#define VS_OFF   (2 * 64 * 65)
#define PS_OFF   (2 * 64 * 65 + 64 * 64)
#define SMEM_FLOATS (2 * 64 * 65 + 64 * 64 + 64 * 65)   // 16576 floats = 66304 B

__global__ void __launch_bounds__(256) flash_attn_kernel(
    const float* __restrict__ qkv, float* __restrict__ y)
{
    extern __shared__ float sm[];
    float* Qs = sm + QS_OFF;
    float* Kt = sm + KT_OFF;
    float* Vs = sm + VS_OFF;
    float* Ps = sm + PS_OFF;

    const int qb = blockIdx.x;
    const int h  = blockIdx.y;
    const int b  = blockIdx.z;
    const int tid = threadIdx.x;
    const int tx = tid & 15, ty = tid >> 4;
    const int r0 = ty * 4;
    const float scale = 0.125f;   // 1/sqrt(64)

    // ---- load Q tile (pre-scaled) ----
    {
        const int lr = tid >> 2;
        const int lcb = (tid & 3) * 16;
        const float* gq = qkv + ((size_t)(b * SS + qb * 64 + lr)) * N_QKV + h * HDD + lcb;
        #pragma unroll
        for (int i = 0; i < 4; i++) {
            float4 v = *(const float4*)(gq + 4 * i);
            float* qs = &Qs[lr * 65 + lcb + 4 * i];
            qs[0] = v.x * scale; qs[1] = v.y * scale;
            qs[2] = v.z * scale; qs[3] = v.w * scale;
        }
    }

    float acc[4][4];
    float m_i[4], l_i[4];
    #pragma unroll
    for (int i = 0; i < 4; i++) {
        m_i[i] = -1e30f; l_i[i] = 0.0f;
        #pragma unroll
        for (int j = 0; j < 4; j++) acc[i][j] = 0.0f;
    }

    for (int kb = 0; kb <= qb; kb++) {
        // ---- load K (transposed) and V tiles ----
        {
            const int lr = tid >> 2;
            const int lcb = (tid & 3) * 16;
            const float* kg = qkv + ((size_t)(b * SS + kb * 64 + lr)) * N_QKV + h * HDD + DD + lcb;
            const float* vg = kg + DD;
            #pragma unroll
            for (int i = 0; i < 4; i++) {
                float4 kv4 = *(const float4*)(kg + 4 * i);
                Kt[(lcb + 4 * i + 0) * 65 + lr] = kv4.x;
                Kt[(lcb + 4 * i + 1) * 65 + lr] = kv4.y;
                Kt[(lcb + 4 * i + 2) * 65 + lr] = kv4.z;
                Kt[(lcb + 4 * i + 3) * 65 + lr] = kv4.w;
                float4 vv = *(const float4*)(vg + 4 * i);
                *(float4*)(&Vs[lr * 64 + lcb + 4 * i]) = vv;
            }
        }
        __syncthreads();

        // ---- S = (Q*scale) @ K^T ----
        float sv[4][4];
        #pragma unroll
        for (int i = 0; i < 4; i++)
            #pragma unroll
            for (int j = 0; j < 4; j++) sv[i][j] = 0.0f;

        #pragma unroll 16
        for (int k = 0; k < 64; k++) {
            float a[4], bb[4];
            #pragma unroll
            for (int i = 0; i < 4; i++) a[i] = Qs[(r0 + i) * 65 + k];
            #pragma unroll
            for (int j = 0; j < 4; j++) bb[j] = Kt[k * 65 + tx + 16 * j];
            #pragma unroll
            for (int i = 0; i < 4; i++)
                #pragma unroll
                for (int j = 0; j < 4; j++)
                    sv[i][j] += a[i] * bb[j];
        }

        // ---- causal mask (only needed on the diagonal block) ----
        if (kb == qb) {
            #pragma unroll
            for (int i = 0; i < 4; i++)
                #pragma unroll
                for (int j = 0; j < 4; j++)
                    if (tx + 16 * j > r0 + i) sv[i][j] = -1e30f;
        }

        // ---- online softmax update ----
        #pragma unroll
        for (int i = 0; i < 4; i++) {
            float mx = fmaxf(fmaxf(sv[i][0], sv[i][1]), fmaxf(sv[i][2], sv[i][3]));
            #pragma unroll
            for (int o = 8; o >= 1; o >>= 1)
                mx = fmaxf(mx, __shfl_xor_sync(0xffffffffu, mx, o));
            float mnew = fmaxf(m_i[i], mx);
            float p0 = __expf(sv[i][0] - mnew);
            float p1 = __expf(sv[i][1] - mnew);
            float p2 = __expf(sv[i][2] - mnew);
            float p3 = __expf(sv[i][3] - mnew);
            float ps = p0 + p1 + p2 + p3;
            #pragma unroll
            for (int o = 8; o >= 1; o >>= 1)
                ps += __shfl_xor_sync(0xffffffffu, ps, o);
            float alpha = __expf(m_i[i] - mnew);
            l_i[i] = l_i[i] * alpha + ps;
            m_i[i] = mnew;
            acc[i][0] *= alpha; acc[i][1] *= alpha;
            acc[i][2] *= alpha; acc[i][3] *= alpha;
            Ps[(r0 + i) * 65 + tx]      = p0;
            Ps[(r0 + i) * 65 + tx + 16] = p1;
            Ps[(r0 + i) * 65 + tx + 32] = p2;
            Ps[(r0 + i) * 65 + tx + 48] = p3;
        }
        __syncthreads();

        // ---- O += P @ V ----
        #pragma unroll 16
        for (int j = 0; j < 64; j++) {
            float p[4], v[4];
            #pragma unroll
            for (int i = 0; i < 4; i++) p[i] = Ps[(r0 + i) * 65 + j];
            #pragma unroll
            for (int c = 0; c < 4; c++) v[c] = Vs[j * 64 + tx + 16 * c];
            #pragma unroll
            for (int i = 0; i < 4; i++)
                #pragma unroll
                for (int c = 0; c < 4; c++)
                    acc[i][c] += p[i] * v[c];
        }
        __syncthreads();
    }

    // ---- epilogue: normalize and write y[b, q, h*64 + c] ----
    #pragma unroll
    for (int i = 0; i < 4; i++) {
        float inv = 1.0f / l_i[i];
        float* yr = y + ((size_t)(b * SS + qb * 64 + r0 + i)) * DD + h * HDD;
        yr[tx]      = acc[i][0] * inv;
        yr[tx + 16] = acc[i][1] * inv;
        yr[tx + 32] = acc[i][2] * inv;
        yr[tx + 48] = acc[i][3] * inv;
    }
}

// ---------------------------------------------------------------------------
extern "C" void kernel_launch(void* const* d_in, const int* in_sizes, int n_in,
                              void* d_out, int out_size)
{
    const float* x      = (const float*)d_in[0];
    const float* W_attn = (const float*)d_in[1];
    const float* b_attn = (const float*)d_in[2];
    const float* W_proj = (const float*)d_in[3];
    const float* b_proj = (const float*)d_in[4];
    float* out = (float*)d_out;

    float* qkv = nullptr;
    float* yb  = nullptr;
    cudaGetSymbolAddress((void**)&qkv, g_qkv);
    cudaGetSymbolAddress((void**)&yb,  g_y);

    cudaFuncSetAttribute(flash_attn_kernel,
                         cudaFuncAttributeMaxDynamicSharedMemorySize,
                         SMEM_FLOATS * sizeof(float));

    // 1) QKV projection: [8192,1024] @ [1024,3072] + bias
    {
        dim3 grid(N_QKV / 128, M_TOT / 128);
        sgemm_bias<<<grid, 256>>>(x, W_attn, b_attn, qkv, M_TOT, N_QKV, DD);
    }

    // 2) causal flash attention -> y [8192, 1024]
    {
        dim3 grid(SS / 64, HH, BB);
        flash_attn_kernel<<<grid, 256, SMEM_FLOATS * sizeof(float)>>>(qkv, yb);
    }

    // 3) output projection: [8192,1024] @ [1024,1024] + bias -> out
    {
        dim3 grid(DD / 128, M_TOT / 128);
        sgemm_bias<<<grid, 256>>>(yb, W_proj, b_proj, out, M_TOT, DD, DD);
    }
}